// round 13
// baseline (speedup 1.0000x reference)
#include <cuda_runtime.h>
#include <cstdint>

#define MM    128   // padded image side
#define NP    64    // patch side
#define NC    4     // channels / positions
#define C0    32    // (M - N) / 2
#define WROW0 11    // first staged image row (fixed layout)
#define WROWS 108   // stage capacity rows 11..118
#define WCOL0 8     // first staged image col (16B-aligned)
#define WCOLS 112   // stage capacity cols 8..119

__device__ __forceinline__ uint32_t smem_u32(const void* p) {
    uint32_t a;
    asm("{ .reg .u64 t; cvta.to.shared.u64 t, %1; cvt.u32.u64 %0, t; }"
        : "=r"(a) : "l"(p));
    return a;
}

// One CTA per image. R12 structure + split-phase pipeline: the window is
// issued as two cp.async commit groups (A = rows needed by output rows 0-31,
// B = rest). Compute of rows 0-31 overlaps group B's DRAM fetch.
__global__ __launch_bounds__(512, 3)
void extract_patches_kernel(const float* __restrict__ img,
                            const float* __restrict__ pos,
                            float* __restrict__ out)
{
    __shared__ __align__(16) float stage[WROWS * WCOLS];   // 48384 B

    const int b = blockIdx.x;
    const float* I = img + (size_t)b * (MM * MM);
    const float* P = pos + (size_t)b * (2 * NC);

    // Uniform (broadcast) position loads; every thread derives identical
    // window bounds. Pad one cell for per-element floor rounding slack.
    float oxv[NC], oyv[NC];
    int ymin = MM, ymax = 0, xmin = MM, xmax = 0, ybmax = 0;
#pragma unroll
    for (int c = 0; c < NC; c++) {
        oxv[c] = __ldg(P + c);
        oyv[c] = __ldg(P + NC + c);
        int yb = (int)floorf((float)C0 + oyv[c]);
        int xb = (int)floorf((float)C0 + oxv[c]);
        ymin = min(ymin, yb - 1);  ymax = max(ymax, yb + NP + 1);
        xmin = min(xmin, xb - 1);  xmax = max(xmax, xb + NP + 1);
        ybmax = max(ybmax, yb);
    }
    // |shift|<20 -> all bounds stay inside the fixed 108x112 stage.

    const int lid  = threadIdx.x + 2 * threadIdx.y + 128 * threadIdx.z;
    const int wid  = lid >> 5;     // 16 warps
    const int lane = lid & 31;

    // ---- Phase 1: two-group streamed fill of the dynamic sub-window ----
    const int r_lo = ymin - WROW0;
    const int r_hi = ymax - WROW0;             // inclusive
    // Group A must cover all taps of output rows 0..31: image rows up to
    // ybmax+33 (floor(x+i) = floor(x)+i, +1 bottom tap, +1 rounding pad).
    const int r_sp = ybmax + 33 - WROW0;       // last row of group A
    const int q_lo = (xmin - WCOL0) >> 2;      // first float4 chunk
    const int q_hi = (xmax - WCOL0) >> 2;      // last float4 chunk
    const bool qact = (lane >= q_lo && lane <= q_hi);

    if (qact) {
        for (int r = r_lo + wid; r <= r_sp; r += 16) {
            uint32_t sdst = smem_u32(stage) + (r * WCOLS + lane * 4) * 4;
            const float* gsrc = I + (WROW0 + r) * MM + WCOL0 + lane * 4;
            asm volatile("cp.async.cg.shared.global [%0], [%1], 16;"
                         :: "r"(sdst), "l"(gsrc) : "memory");
        }
    }
    asm volatile("cp.async.commit_group;" ::: "memory");
    if (qact) {
        for (int r = r_sp + 1 + wid; r <= r_hi; r += 16) {
            uint32_t sdst = smem_u32(stage) + (r * WCOLS + lane * 4) * 4;
            const float* gsrc = I + (WROW0 + r) * MM + WCOL0 + lane * 4;
            asm volatile("cp.async.cg.shared.global [%0], [%1], 16;"
                         :: "r"(sdst), "l"(gsrc) : "memory");
        }
    }
    asm volatile("cp.async.commit_group;" ::: "memory");

    // ---- Per-thread horizontal setup (chunk-independent) ----
    // block (2, 64, 4): tx = channel pair, ty = column, tz = 8-row sub-band.
    const int col = threadIdx.y;
    const int cb  = threadIdx.x * 2;
    float wx[2];
    int xoff[2];
#pragma unroll
    for (int u = 0; u < 2; u++) {
        float xx = (float)(col + C0) + oxv[cb + u];
        float x0 = floorf(xx);
        wx[u]   = xx - x0;
        xoff[u] = (int)x0 - WCOL0;
    }

    // ---- Chunk compute: output rows i0..i0+7 (taps from smem) ----
    auto compute_chunk = [&](int i0) {
        float wy[2], hprev[2];
        int sb[2];
#pragma unroll
        for (int u = 0; u < 2; u++) {
            float yy = (float)(i0 + C0) + oyv[cb + u];
            float y0 = floorf(yy);
            wy[u]   = yy - y0;                 // band-constant (validated R7+)
            int yi  = (int)y0;
            sb[u]   = (yi - WROW0) * WCOLS + xoff[u];
            float a0 = stage[sb[u]];
            float a1 = stage[sb[u] + 1];
            hprev[u] = fmaf(a1 - a0, wx[u], a0);
        }
        float* ob = out + ((size_t)b * (NP * NP) + (size_t)i0 * NP + col) * NC + cb;
#pragma unroll
        for (int k = 0; k < 8; k++) {
            float2 res;
#pragma unroll
            for (int u = 0; u < 2; u++) {
                int idx = sb[u] + (k + 1) * WCOLS;
                float b0 = stage[idx];
                float b1 = stage[idx + 1];
                float hnew = fmaf(b1 - b0, wx[u], b0);
                float r    = fmaf(hnew - hprev[u], wy[u], hprev[u]);
                hprev[u]   = hnew;
                if (u == 0) res.x = r; else res.y = r;
            }
            *reinterpret_cast<float2*>(ob + (size_t)k * (NP * NC)) = res;
        }
    };

    // Wait for group A only, then compute rows 0..31 while group B lands.
    asm volatile("cp.async.wait_group 1;" ::: "memory");
    __syncthreads();
    compute_chunk(threadIdx.z * 8);            // rows 0..31 across tz

    asm volatile("cp.async.wait_group 0;" ::: "memory");
    __syncthreads();
    compute_chunk(32 + threadIdx.z * 8);       // rows 32..63 across tz
}

extern "C" void kernel_launch(void* const* d_in, const int* in_sizes, int n_in,
                              void* d_out, int out_size)
{
    const float* img = (const float*)d_in[0];   // padded_obj (B,128,128,1)
    const float* pos = (const float*)d_in[1];   // positions  (B,1,2,4)
    float* out = (float*)d_out;                 // (B,64,64,4)

    int B = in_sizes[0] / (MM * MM);
    dim3 block(2, 64, 4);
    extract_patches_kernel<<<B, block>>>(img, pos, out);
}

// round 14
// speedup vs baseline: 1.0576x; 1.0576x over previous
#include <cuda_runtime.h>
#include <cstdint>

#define MM    128   // padded image side
#define NP    64    // patch side
#define NC    4     // channels / positions
#define C0    32    // (M - N) / 2
#define RB    16    // rows per thread band
#define WROW0 11    // first staged image row (fixed layout)
#define WROWS 108   // stage capacity rows 11..118
#define WCOL0 8     // first staged image col (16B-aligned)
#define WCOLS 112   // stage capacity cols 8..119

__device__ __forceinline__ uint32_t smem_u32(const void* p) {
    uint32_t a;
    asm("{ .reg .u64 t; cvta.to.shared.u64 t, %1; cvt.u32.u64 %0, t; }"
        : "=r"(a) : "l"(p));
    return a;
}

// One CTA per image = R12 structure exactly, but register-capped to 32
// (__launch_bounds__(512,4)) so 4 CTAs fit the 64K RF -> 64 warps/SM (100%
// occupancy; smem 48.4KB x 4 = 194KB < 228KB). Positions live in smem to
// free registers. Single A/B variable vs R12: occupancy.
__global__ __launch_bounds__(512, 4)
void extract_patches_kernel(const float* __restrict__ img,
                            const float* __restrict__ pos,
                            float* __restrict__ out)
{
    __shared__ __align__(16) float stage[WROWS * WCOLS];   // 48384 B
    __shared__ float spos[2 * NC];
    __shared__ int   sbnd[4];        // r_lo, r_hi, q_lo, q_hi

    const int b = blockIdx.x;
    const float* I = img + (size_t)b * (MM * MM);

    const int lid  = threadIdx.x + 2 * threadIdx.y + 128 * threadIdx.z;
    const int wid  = lid >> 5;     // 16 warps
    const int lane = lid & 31;

    // One warp computes the dynamic window bounds + stages positions.
    if (wid == 0) {
        if (lane < 2 * NC)
            spos[lane] = __ldg(pos + (size_t)b * (2 * NC) + lane);
        __syncwarp();
        if (lane == 0) {
            int ymin = MM, ymax = 0, xmin = MM, xmax = 0;
#pragma unroll
            for (int c = 0; c < NC; c++) {
                // Pad one cell each side for per-element floor rounding slack.
                int yb = (int)floorf((float)C0 + spos[NC + c]);
                int xb = (int)floorf((float)C0 + spos[c]);
                ymin = min(ymin, yb - 1);  ymax = max(ymax, yb + NP + 1);
                xmin = min(xmin, xb - 1);  xmax = max(xmax, xb + NP + 1);
            }
            // |shift|<20 -> bounds stay inside the fixed 108x112 stage.
            sbnd[0] = ymin - WROW0;
            sbnd[1] = ymax - WROW0;            // inclusive
            sbnd[2] = (xmin - WCOL0) >> 2;     // first float4 chunk
            sbnd[3] = (xmax - WCOL0) >> 2;     // last float4 chunk
        }
    }
    __syncthreads();

    // ---- Phase 1: stream the dynamic sub-window into smem ----
    {
        const int r_lo = sbnd[0], r_hi = sbnd[1];
        const int q_lo = sbnd[2], q_hi = sbnd[3];
        if (lane >= q_lo && lane <= q_hi) {
            for (int r = r_lo + wid; r <= r_hi; r += 16) {
                uint32_t sdst = smem_u32(stage) + (r * WCOLS + lane * 4) * 4;
                const float* gsrc = I + (WROW0 + r) * MM + WCOL0 + lane * 4;
                asm volatile("cp.async.cg.shared.global [%0], [%1], 16;"
                             :: "r"(sdst), "l"(gsrc) : "memory");
            }
        }
        asm volatile("cp.async.commit_group;" ::: "memory");
        asm volatile("cp.async.wait_group 0;" ::: "memory");
    }
    __syncthreads();

    // block (2, 64, 4): tx = channel pair, ty = column, tz = 16-row band.
    const int col = threadIdx.y;
    const int i0  = threadIdx.z * RB;
    const int cb  = threadIdx.x * 2;

    // Per-channel setup. wy hoisted to a band constant (validated R7-R13).
    float wx[2], wy[2], hprev[2];
    int sb[2];
#pragma unroll
    for (int u = 0; u < 2; u++) {
        float xx = (float)(col + C0) + spos[cb + u];
        float x0 = floorf(xx);
        wx[u]    = xx - x0;
        int xi   = (int)x0;

        float yy = (float)(i0 + C0) + spos[NC + cb + u];
        float y0 = floorf(yy);
        wy[u]    = yy - y0;
        int yi   = (int)y0;

        sb[u] = (yi - WROW0) * WCOLS + (xi - WCOL0);
        float a0 = stage[sb[u]];
        float a1 = stage[sb[u] + 1];
        hprev[u] = fmaf(a1 - a0, wx[u], a0);   // H(top row)
    }

    // Output: (B, 64, 64, 4); warp-contiguous full-sector float2 stores.
    float* ob = out + ((size_t)b * (NP * NP) + (size_t)i0 * NP + col) * NC + cb;

#pragma unroll
    for (int k = 0; k < RB; k++) {
        float2 res;
#pragma unroll
        for (int u = 0; u < 2; u++) {
            int idx = sb[u] + (k + 1) * WCOLS;
            float b0 = stage[idx];
            float b1 = stage[idx + 1];
            float hnew = fmaf(b1 - b0, wx[u], b0);      // H(bottom row)
            float r    = fmaf(hnew - hprev[u], wy[u], hprev[u]);
            hprev[u]   = hnew;
            if (u == 0) res.x = r; else res.y = r;
        }
        // Write-back store (R10+ winner): L2 coalesces full lines.
        *reinterpret_cast<float2*>(ob + (size_t)k * (NP * NC)) = res;
    }
}

extern "C" void kernel_launch(void* const* d_in, const int* in_sizes, int n_in,
                              void* d_out, int out_size)
{
    const float* img = (const float*)d_in[0];   // padded_obj (B,128,128,1)
    const float* pos = (const float*)d_in[1];   // positions  (B,1,2,4)
    float* out = (float*)d_out;                 // (B,64,64,4)

    int B = in_sizes[0] / (MM * MM);
    dim3 block(2, 64, 4);
    extract_patches_kernel<<<B, block>>>(img, pos, out);
}